// round 8
// baseline (speedup 1.0000x reference)
#include <cuda_runtime.h>
#include <cstdint>
#include <cstddef>

// LISTA-CPSS: B=16384, M=256, N=1024, DEPTH=16
// Exact fp32 GEMMs on the Blackwell packed FFMA2 pipe (fma.rn.f32x2),
// duplicated-A smem (zero-mov operand packing) + register-prefetch pipeline.

#define B_DIM  16384
#define M_DIM  256
#define N_DIM  1024
#define DEPTH  16

// Scratch (allocation-free)
__device__ float g_r[(size_t)B_DIM * M_DIM];   // 16.7 MB
__device__ float g_v[(size_t)B_DIM * N_DIM];   // 67 MB
__device__ float g_u[(size_t)B_DIM * N_DIM];   // 67 MB

typedef unsigned long long ull;

__device__ __forceinline__ void ffma2(ull& d, ull a, ull b) {
    asm("fma.rn.f32x2 %0, %1, %2, %0;" : "+l"(d) : "l"(a), "l"(b));
}

// smem: X duplicated ({a,a} pairs), Y plain; k-major
#define XPITCH 264   // 256 dup floats + 8 pad
#define YPITCH 132   // 128 floats + 4 pad

// ---------------------------------------------------------------------------
// C[i,j] = epilogue( sum_k X[i,k]*Y[j,k] ), X:[I,K] Y:[J,K] both k-contig.
// MODE 0: C = bias - acc   (r = x - u A^T)
// MODE 1: C = bias + acc   (v = u + r W^T)
// MODE 2: C = acc          (iter 0)
// Tile 128x128, BK=8, 256 threads, 8x8/thread via f32x2 packed FMA.
// ---------------------------------------------------------------------------
template <int MODE>
__global__ void __launch_bounds__(256, 2)
gemm_f32x2(const float* __restrict__ X, const float* __restrict__ Y,
           const float* __restrict__ bias, float* __restrict__ C,
           int K, int ldc)
{
    __shared__ float sXd[8][XPITCH];   // duplicated: sXd[k][2r]=sXd[k][2r+1]=X[r][k]
    __shared__ float sY [8][YPITCH];

    const int bi  = blockIdx.x;
    const int bj  = blockIdx.y;
    const int tid = threadIdx.x;

    const int loadRow = tid >> 1;          // 0..127
    const int loadK4  = (tid & 1) * 4;     // 0 or 4

    const float* xg = X + (size_t)(bi * 128 + loadRow) * K + loadK4;
    const float* yg = Y + (size_t)(bj * 128 + loadRow) * K + loadK4;

    const int tx = tid & 15;               // n: 8 cols each
    const int ty = tid >> 4;               // m: 8 rows each

    ull acc[8][4];
#pragma unroll
    for (int p = 0; p < 8; ++p)
#pragma unroll
        for (int q = 0; q < 4; ++q) acc[p][q] = 0ull;

    const int nch = K >> 3;

    float4 xv = *reinterpret_cast<const float4*>(xg);
    float4 yv = *reinterpret_cast<const float4*>(yg);

#pragma unroll 1
    for (int ch = 0; ch < nch; ++ch) {
        __syncthreads();
        // store duplicated X ({v,v} float2) and plain Y
        {
            const float xa[4] = {xv.x, xv.y, xv.z, xv.w};
            const float ya[4] = {yv.x, yv.y, yv.z, yv.w};
#pragma unroll
            for (int i = 0; i < 4; ++i) {
                *reinterpret_cast<float2*>(&sXd[loadK4 + i][2 * loadRow]) =
                    make_float2(xa[i], xa[i]);
                sY[loadK4 + i][loadRow] = ya[i];
            }
        }
        __syncthreads();

        // prefetch next chunk into registers (hidden behind compute)
        if (ch + 1 < nch) {
            xv = *reinterpret_cast<const float4*>(xg + (ch + 1) * 8);
            yv = *reinterpret_cast<const float4*>(yg + (ch + 1) * 8);
        }

#pragma unroll
        for (int k = 0; k < 8; ++k) {
            ull adup[8];
#pragma unroll
            for (int j = 0; j < 4; ++j) {
                const ulonglong2 t =
                    *reinterpret_cast<const ulonglong2*>(&sXd[k][ty * 16 + j * 4]);
                adup[2 * j]     = t.x;
                adup[2 * j + 1] = t.y;
            }
            const ulonglong2 b01 =
                *reinterpret_cast<const ulonglong2*>(&sY[k][tx * 8]);
            const ulonglong2 b23 =
                *reinterpret_cast<const ulonglong2*>(&sY[k][tx * 8 + 4]);
#pragma unroll
            for (int p = 0; p < 8; ++p) {
                ffma2(acc[p][0], adup[p], b01.x);
                ffma2(acc[p][1], adup[p], b01.y);
                ffma2(acc[p][2], adup[p], b23.x);
                ffma2(acc[p][3], adup[p], b23.y);
            }
        }
    }

    // epilogue
    const int ci = bi * 128 + ty * 8;
    const int cj = bj * 128 + tx * 8;
#pragma unroll
    for (int p = 0; p < 8; ++p) {
        const size_t base = (size_t)(ci + p) * ldc + cj;
        const float* af = reinterpret_cast<const float*>(acc[p]);   // 8 floats
#pragma unroll
        for (int q0 = 0; q0 < 8; q0 += 4) {
            float4 o;
            float* po = reinterpret_cast<float*>(&o);
#pragma unroll
            for (int q = 0; q < 4; ++q) {
                float v = af[q0 + q];
                if (MODE == 0)      v = bias[base + q0 + q] - v;
                else if (MODE == 1) v = bias[base + q0 + q] + v;
                po[q] = v;
            }
            *reinterpret_cast<float4*>(C + base + q0) = o;
        }
    }
}

// ---------------------------------------------------------------------------
// select_shrink: exact k-th largest |v| per row (bit-exact radix select on
// float bits), then u = mask ? v : soft-threshold(v).
// ---------------------------------------------------------------------------
__global__ void __launch_bounds__(256)
select_shrink(const float* __restrict__ V, float* __restrict__ U,
              const float* __restrict__ thr, int iter, int kth)
{
    __shared__ unsigned s_abs[1024];
    __shared__ unsigned s_hist[256];
    __shared__ unsigned s_sel[2];

    const int row = blockIdx.x;
    const int tid = threadIdx.x;

    const float4 vv = reinterpret_cast<const float4*>(V + (size_t)row * N_DIM)[tid];
    float va[4] = {vv.x, vv.y, vv.z, vv.w};
#pragma unroll
    for (int e = 0; e < 4; ++e)
        s_abs[e * 256 + tid] = __float_as_uint(fabsf(va[e]));

    unsigned prefix = 0, remaining = (unsigned)kth;

#pragma unroll 1
    for (int pass = 0; pass < 4; ++pass) {
        const int shift = 24 - pass * 8;
        const unsigned hmask = (pass == 0) ? 0u : (0xFFFFFFFFu << (shift + 8));

        s_hist[tid] = 0;
        __syncthreads();
#pragma unroll
        for (int e = 0; e < 4; ++e) {
            const unsigned b = s_abs[e * 256 + tid];
            if ((b & hmask) == prefix) atomicAdd(&s_hist[(b >> shift) & 255u], 1u);
        }
        __syncthreads();

        if (tid < 32) {
            unsigned v[8], ls[8];
#pragma unroll
            for (int i = 0; i < 8; ++i) v[i] = s_hist[tid * 8 + i];
            ls[7] = v[7];
#pragma unroll
            for (int i = 6; i >= 0; --i) ls[i] = v[i] + ls[i + 1];
            const unsigned tot = ls[0];
            unsigned suf = tot;
#pragma unroll
            for (int dd = 1; dd < 32; dd <<= 1) {
                const unsigned t = __shfl_down_sync(0xFFFFFFFFu, suf, dd);
                if (tid + dd < 32) suf += t;
            }
            const unsigned above = suf - tot;
#pragma unroll
            for (int i = 0; i < 8; ++i) {
                const unsigned sb_ = above + ls[i];
                const unsigned sn  = above + ((i < 7) ? ls[i + 1] : 0u);
                if (sb_ >= remaining && sn < remaining) {
                    s_sel[0] = prefix | ((unsigned)(tid * 8 + i) << shift);
                    s_sel[1] = remaining - sn;
                }
            }
        }
        __syncthreads();
        prefix    = s_sel[0];
        remaining = s_sel[1];
    }

    const float th = __uint_as_float(prefix);
    const float t  = thr[iter];

    float4 ov;
    float* po = reinterpret_cast<float*>(&ov);
#pragma unroll
    for (int e = 0; e < 4; ++e) {
        const float x = va[e];
        const float a = fabsf(x);
        po[e] = (a >= t && a >= th) ? x : copysignf(fmaxf(a - t, 0.0f), x);
    }
    reinterpret_cast<float4*>(U + (size_t)row * N_DIM)[tid] = ov;
}

// ---------------------------------------------------------------------------
extern "C" void kernel_launch(void* const* d_in, const int* in_sizes, int n_in,
                              void* d_out, int out_size)
{
    const float* x   = (const float*)d_in[0];   // [B, M]
    const float* A   = (const float*)d_in[1];   // [M, N]
    const float* W   = (const float*)d_in[2];   // [DEPTH, N, M]
    const float* thr = (const float*)d_in[3];   // [DEPTH]
    float* uout = (float*)d_out;                // [B, N]

    float *rp, *vp, *up;
    cudaGetSymbolAddress((void**)&rp, g_r);
    cudaGetSymbolAddress((void**)&vp, g_v);
    cudaGetSymbolAddress((void**)&up, g_u);

    // kth_i = 1024 - (ceil((100 - p_i)/100 * 1024) - 1), p_i = min((i+1)*1.2, 5)
    static const int KTH[DEPTH] = {13, 25, 37, 50, 52, 52, 52, 52,
                                   52, 52, 52, 52, 52, 52, 52, 52};

    const dim3 blk(256);
    const dim3 gR(B_DIM / 128, M_DIM / 128);   // (128, 2)
    const dim3 gV(B_DIM / 128, N_DIM / 128);   // (128, 8)

    // ---- iteration 0: u = 0  =>  v = x @ W0^T ----
    gemm_f32x2<2><<<gV, blk>>>(x, W, nullptr, vp, M_DIM, N_DIM);
    select_shrink<<<B_DIM, blk>>>(vp, up, thr, 0, KTH[0]);

    // ---- iterations 1..15 ----
    for (int i = 1; i < DEPTH; ++i) {
        // r = x - u @ A^T
        gemm_f32x2<0><<<gR, blk>>>(up, A, x, rp, N_DIM, M_DIM);
        // v = u + r @ W[i]^T
        gemm_f32x2<1><<<gV, blk>>>(rp, W + (size_t)i * N_DIM * M_DIM, up, vp,
                                   M_DIM, N_DIM);
        // u = shrinkss(v); last iteration writes straight to d_out
        select_shrink<<<B_DIM, blk>>>(vp, (i == DEPTH - 1) ? uout : up,
                                      thr, i, KTH[i]);
    }
}

// round 10
// speedup vs baseline: 1.2979x; 1.2979x over previous
#include <cuda_runtime.h>
#include <cstdint>
#include <cstddef>

// LISTA-CPSS: B=16384, M=256, N=1024, DEPTH=16
// Exact fp32 SIMT GEMM (BK=16, reduced syncs) + 2-phase bit-exact radix select.

#define B_DIM  16384
#define M_DIM  256
#define N_DIM  1024
#define DEPTH  16

__device__ float g_r[(size_t)B_DIM * M_DIM];
__device__ float g_v[(size_t)B_DIM * N_DIM];
__device__ float g_u[(size_t)B_DIM * N_DIM];

// ---------------------------------------------------------------------------
// Tiled SGEMM: C[i,j] = epilogue( sum_k X[i,k]*Y[j,k] );  X:[I,K], Y:[J,K].
// MODE 0: C = bias - acc ; MODE 1: C = bias + acc ; MODE 2: C = acc
// 128x128 tile, BK=16, 256 threads, 8x8/thread, register-prefetch pipeline.
// Per-thread k-order identical to the validated R2 kernel (bit-exact result).
// ---------------------------------------------------------------------------
template <int MODE>
__global__ void __launch_bounds__(256, 2)
gemm_nt(const float* __restrict__ X, const float* __restrict__ Y,
        const float* __restrict__ bias, float* __restrict__ C,
        int K, int ldc)
{
    __shared__ float sX[16][132];
    __shared__ float sY[16][132];

    const int bi  = blockIdx.x;
    const int bj  = blockIdx.y;
    const int tid = threadIdx.x;

    const int loadRow = tid >> 1;          // 0..127
    const int kBase   = (tid & 1) * 8;     // 0 or 8

    const float* xg = X + (size_t)(bi * 128 + loadRow) * K + kBase;
    const float* yg = Y + (size_t)(bj * 128 + loadRow) * K + kBase;

    const int tx = tid & 15;
    const int ty = tid >> 4;

    float acc[8][8];
#pragma unroll
    for (int p = 0; p < 8; ++p)
#pragma unroll
        for (int q = 0; q < 8; ++q) acc[p][q] = 0.0f;

    const int nch = K >> 4;   // chunks of 16

    float4 xv0 = *reinterpret_cast<const float4*>(xg);
    float4 xv1 = *reinterpret_cast<const float4*>(xg + 4);
    float4 yv0 = *reinterpret_cast<const float4*>(yg);
    float4 yv1 = *reinterpret_cast<const float4*>(yg + 4);

#pragma unroll 1
    for (int ch = 0; ch < nch; ++ch) {
        __syncthreads();
        {
            const float xa[8] = {xv0.x, xv0.y, xv0.z, xv0.w, xv1.x, xv1.y, xv1.z, xv1.w};
            const float ya[8] = {yv0.x, yv0.y, yv0.z, yv0.w, yv1.x, yv1.y, yv1.z, yv1.w};
#pragma unroll
            for (int i = 0; i < 8; ++i) {
                sX[kBase + i][loadRow] = xa[i];
                sY[kBase + i][loadRow] = ya[i];
            }
        }
        __syncthreads();

        if (ch + 1 < nch) {
            const float* xn = xg + (ch + 1) * 16;
            const float* yn = yg + (ch + 1) * 16;
            xv0 = *reinterpret_cast<const float4*>(xn);
            xv1 = *reinterpret_cast<const float4*>(xn + 4);
            yv0 = *reinterpret_cast<const float4*>(yn);
            yv1 = *reinterpret_cast<const float4*>(yn + 4);
        }

#pragma unroll
        for (int k = 0; k < 16; ++k) {
            float a[8], b[8];
#pragma unroll
            for (int p = 0; p < 8; ++p) a[p] = sX[k][ty * 8 + p];
#pragma unroll
            for (int q = 0; q < 8; ++q) b[q] = sY[k][tx * 8 + q];
#pragma unroll
            for (int p = 0; p < 8; ++p)
#pragma unroll
                for (int q = 0; q < 8; ++q) acc[p][q] += a[p] * b[q];
        }
    }

    const int ci = bi * 128 + ty * 8;
    const int cj = bj * 128 + tx * 8;
#pragma unroll
    for (int p = 0; p < 8; ++p) {
        const size_t base = (size_t)(ci + p) * ldc + cj;
#pragma unroll
        for (int q0 = 0; q0 < 8; q0 += 4) {
            float4 o;
            float* po = reinterpret_cast<float*>(&o);
#pragma unroll
            for (int q = 0; q < 4; ++q) {
                float v = acc[p][q0 + q];
                if (MODE == 0)      v = bias[base + q0 + q] - v;
                else if (MODE == 1) v = bias[base + q0 + q] + v;
                po[q] = v;
            }
            *reinterpret_cast<float4*>(C + base + q0) = o;
        }
    }
}

// ---------------------------------------------------------------------------
// select_shrink: bit-exact k-th largest |v| per row, 2-phase:
//   Phase A: 1024-bin histogram over top-11 bits of the float pattern,
//            block suffix-scan -> boundary bin + remaining rank.
//   Phase B: collect boundary-bin candidates, 3 radix passes (8/8/5 bits)
//            over the (small) candidate list -> exact threshold bits.
// Then masked soft-threshold.
// ---------------------------------------------------------------------------
__global__ void __launch_bounds__(256)
select_shrink(const float* __restrict__ V, float* __restrict__ U,
              const float* __restrict__ thr, int iter, int kth)
{
    __shared__ unsigned s_hist[1024];
    __shared__ unsigned s_cand[1024];
    __shared__ unsigned s_wtot[8];
    __shared__ unsigned s_wabove[8];
    __shared__ unsigned s_sel[2];
    __shared__ unsigned s_cnt;

    const int row  = blockIdx.x;
    const int tid  = threadIdx.x;
    const int lane = tid & 31;
    const int wrp  = tid >> 5;

    const float4 vv = reinterpret_cast<const float4*>(V + (size_t)row * N_DIM)[tid];
    float va[4] = {vv.x, vv.y, vv.z, vv.w};
    unsigned key[4];
#pragma unroll
    for (int e = 0; e < 4; ++e) key[e] = __float_as_uint(fabsf(va[e]));

    // ---- Phase A: coarse histogram (bins = key >> 21, 0..1023) ----
#pragma unroll
    for (int i = 0; i < 4; ++i) s_hist[tid * 4 + i] = 0;
    __syncthreads();
#pragma unroll
    for (int e = 0; e < 4; ++e) atomicAdd(&s_hist[key[e] >> 21], 1u);
    __syncthreads();

    // suffix scan over 1024 bins: thread t owns bins 4t..4t+3
    unsigned h[4], ls[4];
#pragma unroll
    for (int i = 0; i < 4; ++i) h[i] = s_hist[tid * 4 + i];
    ls[3] = h[3];
#pragma unroll
    for (int i = 2; i >= 0; --i) ls[i] = h[i] + ls[i + 1];
    const unsigned tot = ls[0];

    unsigned suf = tot;   // inclusive suffix over lanes >= lane within warp
#pragma unroll
    for (int d = 1; d < 32; d <<= 1) {
        const unsigned t = __shfl_down_sync(0xFFFFFFFFu, suf, d);
        if (lane + d < 32) suf += t;
    }
    if (lane == 0) s_wtot[wrp] = suf;
    __syncthreads();
    if (tid == 0) {
        unsigned run = 0;
        for (int w = 7; w >= 0; --w) { s_wabove[w] = run; run += s_wtot[w]; }
    }
    __syncthreads();

    {
        const unsigned A = s_wabove[wrp] + (suf - tot);   // suffix(4t+4)
        const unsigned k = (unsigned)kth;
#pragma unroll
        for (int i = 0; i < 4; ++i) {
            const unsigned sb = A + ls[i];
            const unsigned sn = (i < 3) ? (A + ls[i + 1]) : A;
            if (sb >= k && sn < k) {
                s_sel[0] = (unsigned)(tid * 4 + i);   // boundary bin
                s_sel[1] = k - sn;                    // remaining rank in bin
            }
        }
    }
    __syncthreads();
    const unsigned selbin = s_sel[0];
    unsigned rem          = s_sel[1];

    // ---- Phase B: collect candidates in boundary bin ----
    if (tid == 0) s_cnt = 0;
    __syncthreads();
#pragma unroll
    for (int e = 0; e < 4; ++e) {
        if ((key[e] >> 21) == selbin) {
            const unsigned idx = atomicAdd(&s_cnt, 1u);
            s_cand[idx] = key[e];
        }
    }
    __syncthreads();
    const unsigned c = s_cnt;

    unsigned prefix = selbin << 21;
    const int SHIFT[3] = {13, 5, 0};
    const unsigned HIMASK[3] = {0xFFE00000u, 0xFFFFE000u, 0xFFFFFFE0u};
    const unsigned BMASK[3]  = {255u, 255u, 31u};

#pragma unroll 1
    for (int pass = 0; pass < 3; ++pass) {
        if (tid < 256) s_hist[tid] = 0;
        __syncthreads();
        for (unsigned j = tid; j < c; j += 256) {
            const unsigned kk = s_cand[j];
            if ((kk & HIMASK[pass]) == prefix)
                atomicAdd(&s_hist[(kk >> SHIFT[pass]) & BMASK[pass]], 1u);
        }
        __syncthreads();

        if (tid < 32) {
            unsigned v8[8], l8[8];
#pragma unroll
            for (int i = 0; i < 8; ++i) v8[i] = s_hist[tid * 8 + i];
            l8[7] = v8[7];
#pragma unroll
            for (int i = 6; i >= 0; --i) l8[i] = v8[i] + l8[i + 1];
            const unsigned t8 = l8[0];
            unsigned sf = t8;
#pragma unroll
            for (int d = 1; d < 32; d <<= 1) {
                const unsigned t = __shfl_down_sync(0xFFFFFFFFu, sf, d);
                if (tid + d < 32) sf += t;
            }
            const unsigned above = sf - t8;
#pragma unroll
            for (int i = 0; i < 8; ++i) {
                const unsigned sb = above + l8[i];
                const unsigned sn = above + ((i < 7) ? l8[i + 1] : 0u);
                if (sb >= rem && sn < rem) {
                    s_sel[0] = (unsigned)(tid * 8 + i);
                    s_sel[1] = rem - sn;
                }
            }
        }
        __syncthreads();
        prefix |= s_sel[0] << SHIFT[pass];
        rem     = s_sel[1];
        __syncthreads();
    }

    const float th = __uint_as_float(prefix);
    const float t  = thr[iter];

    float4 ov;
    float* po = reinterpret_cast<float*>(&ov);
#pragma unroll
    for (int e = 0; e < 4; ++e) {
        const float x = va[e];
        const float a = fabsf(x);
        po[e] = (a >= t && a >= th) ? x : copysignf(fmaxf(a - t, 0.0f), x);
    }
    reinterpret_cast<float4*>(U + (size_t)row * N_DIM)[tid] = ov;
}

// ---------------------------------------------------------------------------
extern "C" void kernel_launch(void* const* d_in, const int* in_sizes, int n_in,
                              void* d_out, int out_size)
{
    const float* x   = (const float*)d_in[0];   // [B, M]
    const float* A   = (const float*)d_in[1];   // [M, N]
    const float* W   = (const float*)d_in[2];   // [DEPTH, N, M]
    const float* thr = (const float*)d_in[3];   // [DEPTH]
    float* uout = (float*)d_out;                // [B, N]

    float *rp, *vp, *up;
    cudaGetSymbolAddress((void**)&rp, g_r);
    cudaGetSymbolAddress((void**)&vp, g_v);
    cudaGetSymbolAddress((void**)&up, g_u);

    // kth_i = 1024 - (ceil((100 - p_i)/100 * 1024) - 1), p_i = min((i+1)*1.2, 5)
    static const int KTH[DEPTH] = {13, 25, 37, 50, 52, 52, 52, 52,
                                   52, 52, 52, 52, 52, 52, 52, 52};

    const dim3 blk(256);
    const dim3 gR(B_DIM / 128, M_DIM / 128);   // (128, 2)
    const dim3 gV(B_DIM / 128, N_DIM / 128);   // (128, 8)

    // ---- iteration 0: u = 0  =>  v = x @ W0^T ----
    gemm_nt<2><<<gV, blk>>>(x, W, nullptr, vp, M_DIM, N_DIM);
    select_shrink<<<B_DIM, blk>>>(vp, up, thr, 0, KTH[0]);

    // ---- iterations 1..15 ----
    for (int i = 1; i < DEPTH; ++i) {
        // r = x - u @ A^T
        gemm_nt<0><<<gR, blk>>>(up, A, x, rp, N_DIM, M_DIM);
        // v = u + r @ W[i]^T
        gemm_nt<1><<<gV, blk>>>(rp, W + (size_t)i * N_DIM * M_DIM, up, vp,
                                M_DIM, N_DIM);
        // u = shrinkss(v); last iteration writes straight to d_out
        select_shrink<<<B_DIM, blk>>>(vp, (i == DEPTH - 1) ? uout : up,
                                      thr, i, KTH[i]);
    }
}

// round 11
// speedup vs baseline: 1.5095x; 1.1631x over previous
#include <cuda_runtime.h>
#include <cstdint>
#include <cstddef>

// LISTA-CPSS: B=16384, M=256, N=1024, DEPTH=16
// Exact fp32 SIMT GEMM: 32x64 warp tiles, single-wavefront aligned LDS.128,
// BK=16, register-prefetch. + 2-phase bit-exact radix select.

#define B_DIM  16384
#define M_DIM  256
#define N_DIM  1024
#define DEPTH  16

__device__ float g_r[(size_t)B_DIM * M_DIM];
__device__ float g_v[(size_t)B_DIM * N_DIM];
__device__ float g_u[(size_t)B_DIM * N_DIM];

// ---------------------------------------------------------------------------
// Tiled SGEMM: C[i,j] = epilogue( sum_k X[i,k]*Y[j,k] );  X:[I,K], Y:[J,K].
// MODE 0: C = bias - acc ; MODE 1: C = bias + acc ; MODE 2: C = acc
// 128x128 tile, BK=16, 256 threads. Warp tile 32x64 (4x2 warp grid); thread
// fragment = 2x float4 rows + 2x float4 cols -> all LDS.128 are one aligned
// wavefront (a: 64B bcast, b: 128B contiguous), pitch 128 (no pad needed).
// Per-element k-order identical to R2/R10 kernels (bit-exact result).
// ---------------------------------------------------------------------------
template <int MODE>
__global__ void __launch_bounds__(256, 2)
gemm_nt(const float* __restrict__ X, const float* __restrict__ Y,
        const float* __restrict__ bias, float* __restrict__ C,
        int K, int ldc)
{
    __shared__ float sX[16][128];
    __shared__ float sY[16][128];

    const int bi  = blockIdx.x;
    const int bj  = blockIdx.y;
    const int tid = threadIdx.x;

    // ---- global -> smem loader mapping ----
    const int loadRow = tid >> 1;          // 0..127
    const int kBase   = (tid & 1) * 8;     // 0 or 8

    const float* xg = X + (size_t)(bi * 128 + loadRow) * K + kBase;
    const float* yg = Y + (size_t)(bj * 128 + loadRow) * K + kBase;

    // ---- compute mapping: warp tile 32x64, lane tile 8x8 (2+2 float4) ----
    const int lane = tid & 31;
    const int warp = tid >> 5;
    const int wy = warp & 3;               // 4 row groups of 32
    const int wx = warp >> 2;              // 2 col groups of 64
    const int ty = lane >> 3;              // 0..3
    const int tx = lane & 7;               // 0..7

    const int r0 = wy * 32 + ty * 4;       // rows r0..r0+3
    const int r1 = r0 + 16;                // rows r1..r1+3
    const int c0 = wx * 64 + tx * 4;       // cols c0..c0+3
    const int c1 = c0 + 32;                // cols c1..c1+3

    float acc[8][8];
#pragma unroll
    for (int p = 0; p < 8; ++p)
#pragma unroll
        for (int q = 0; q < 8; ++q) acc[p][q] = 0.0f;

    const int nch = K >> 4;   // chunks of 16

    float4 xv0 = *reinterpret_cast<const float4*>(xg);
    float4 xv1 = *reinterpret_cast<const float4*>(xg + 4);
    float4 yv0 = *reinterpret_cast<const float4*>(yg);
    float4 yv1 = *reinterpret_cast<const float4*>(yg + 4);

#pragma unroll 1
    for (int ch = 0; ch < nch; ++ch) {
        __syncthreads();
        {
            const float xa[8] = {xv0.x, xv0.y, xv0.z, xv0.w, xv1.x, xv1.y, xv1.z, xv1.w};
            const float ya[8] = {yv0.x, yv0.y, yv0.z, yv0.w, yv1.x, yv1.y, yv1.z, yv1.w};
#pragma unroll
            for (int i = 0; i < 8; ++i) {
                sX[kBase + i][loadRow] = xa[i];
                sY[kBase + i][loadRow] = ya[i];
            }
        }
        __syncthreads();

        if (ch + 1 < nch) {
            const float* xn = xg + (ch + 1) * 16;
            const float* yn = yg + (ch + 1) * 16;
            xv0 = *reinterpret_cast<const float4*>(xn);
            xv1 = *reinterpret_cast<const float4*>(xn + 4);
            yv0 = *reinterpret_cast<const float4*>(yn);
            yv1 = *reinterpret_cast<const float4*>(yn + 4);
        }

#pragma unroll
        for (int k = 0; k < 16; ++k) {
            const float4 a0 = *reinterpret_cast<const float4*>(&sX[k][r0]);
            const float4 a1 = *reinterpret_cast<const float4*>(&sX[k][r1]);
            const float4 b0 = *reinterpret_cast<const float4*>(&sY[k][c0]);
            const float4 b1 = *reinterpret_cast<const float4*>(&sY[k][c1]);
            const float a[8] = {a0.x, a0.y, a0.z, a0.w, a1.x, a1.y, a1.z, a1.w};
            const float b[8] = {b0.x, b0.y, b0.z, b0.w, b1.x, b1.y, b1.z, b1.w};
#pragma unroll
            for (int p = 0; p < 8; ++p)
#pragma unroll
                for (int q = 0; q < 8; ++q) acc[p][q] += a[p] * b[q];
        }
    }

    // ---- epilogue: rows {r0..r0+3, r1..r1+3}, col segments c0, c1 ----
    const int gr0 = bi * 128;
    const int gc0 = bj * 128;
#pragma unroll
    for (int p = 0; p < 8; ++p) {
        const int rr = gr0 + ((p < 4) ? (r0 + p) : (r1 + p - 4));
#pragma unroll
        for (int half = 0; half < 2; ++half) {
            const int cc = gc0 + ((half == 0) ? c0 : c1);
            const size_t base = (size_t)rr * ldc + cc;
            float4 o;
            float* po = reinterpret_cast<float*>(&o);
#pragma unroll
            for (int q = 0; q < 4; ++q) {
                float v = acc[p][half * 4 + q];
                if (MODE == 0)      v = bias[base + q] - v;
                else if (MODE == 1) v = bias[base + q] + v;
                po[q] = v;
            }
            *reinterpret_cast<float4*>(C + base) = o;
        }
    }
}

// ---------------------------------------------------------------------------
// select_shrink: bit-exact k-th largest |v| per row, 2-phase:
//   Phase A: 1024-bin histogram over top-11 bits + block suffix-scan.
//   Phase B: boundary-bin candidates, 3 radix passes over the small list.
// Then masked soft-threshold.
// ---------------------------------------------------------------------------
__global__ void __launch_bounds__(256)
select_shrink(const float* __restrict__ V, float* __restrict__ U,
              const float* __restrict__ thr, int iter, int kth)
{
    __shared__ unsigned s_hist[1024];
    __shared__ unsigned s_cand[1024];
    __shared__ unsigned s_wtot[8];
    __shared__ unsigned s_wabove[8];
    __shared__ unsigned s_sel[2];
    __shared__ unsigned s_cnt;

    const int row  = blockIdx.x;
    const int tid  = threadIdx.x;
    const int lane = tid & 31;
    const int wrp  = tid >> 5;

    const float4 vv = reinterpret_cast<const float4*>(V + (size_t)row * N_DIM)[tid];
    float va[4] = {vv.x, vv.y, vv.z, vv.w};
    unsigned key[4];
#pragma unroll
    for (int e = 0; e < 4; ++e) key[e] = __float_as_uint(fabsf(va[e]));

    // ---- Phase A ----
#pragma unroll
    for (int i = 0; i < 4; ++i) s_hist[tid * 4 + i] = 0;
    __syncthreads();
#pragma unroll
    for (int e = 0; e < 4; ++e) atomicAdd(&s_hist[key[e] >> 21], 1u);
    __syncthreads();

    unsigned h[4], ls[4];
#pragma unroll
    for (int i = 0; i < 4; ++i) h[i] = s_hist[tid * 4 + i];
    ls[3] = h[3];
#pragma unroll
    for (int i = 2; i >= 0; --i) ls[i] = h[i] + ls[i + 1];
    const unsigned tot = ls[0];

    unsigned suf = tot;
#pragma unroll
    for (int d = 1; d < 32; d <<= 1) {
        const unsigned t = __shfl_down_sync(0xFFFFFFFFu, suf, d);
        if (lane + d < 32) suf += t;
    }
    if (lane == 0) s_wtot[wrp] = suf;
    __syncthreads();
    if (tid == 0) {
        unsigned run = 0;
        for (int w = 7; w >= 0; --w) { s_wabove[w] = run; run += s_wtot[w]; }
    }
    __syncthreads();

    {
        const unsigned A = s_wabove[wrp] + (suf - tot);
        const unsigned k = (unsigned)kth;
#pragma unroll
        for (int i = 0; i < 4; ++i) {
            const unsigned sb = A + ls[i];
            const unsigned sn = (i < 3) ? (A + ls[i + 1]) : A;
            if (sb >= k && sn < k) {
                s_sel[0] = (unsigned)(tid * 4 + i);
                s_sel[1] = k - sn;
            }
        }
    }
    __syncthreads();
    const unsigned selbin = s_sel[0];
    unsigned rem          = s_sel[1];

    // ---- Phase B ----
    if (tid == 0) s_cnt = 0;
    __syncthreads();
#pragma unroll
    for (int e = 0; e < 4; ++e) {
        if ((key[e] >> 21) == selbin) {
            const unsigned idx = atomicAdd(&s_cnt, 1u);
            s_cand[idx] = key[e];
        }
    }
    __syncthreads();
    const unsigned c = s_cnt;

    unsigned prefix = selbin << 21;
    const int SHIFT[3] = {13, 5, 0};
    const unsigned HIMASK[3] = {0xFFE00000u, 0xFFFFE000u, 0xFFFFFFE0u};
    const unsigned BMASK[3]  = {255u, 255u, 31u};

#pragma unroll 1
    for (int pass = 0; pass < 3; ++pass) {
        if (tid < 256) s_hist[tid] = 0;
        __syncthreads();
        for (unsigned j = tid; j < c; j += 256) {
            const unsigned kk = s_cand[j];
            if ((kk & HIMASK[pass]) == prefix)
                atomicAdd(&s_hist[(kk >> SHIFT[pass]) & BMASK[pass]], 1u);
        }
        __syncthreads();

        if (tid < 32) {
            unsigned v8[8], l8[8];
#pragma unroll
            for (int i = 0; i < 8; ++i) v8[i] = s_hist[tid * 8 + i];
            l8[7] = v8[7];
#pragma unroll
            for (int i = 6; i >= 0; --i) l8[i] = v8[i] + l8[i + 1];
            const unsigned t8 = l8[0];
            unsigned sf = t8;
#pragma unroll
            for (int d = 1; d < 32; d <<= 1) {
                const unsigned t = __shfl_down_sync(0xFFFFFFFFu, sf, d);
                if (tid + d < 32) sf += t;
            }
            const unsigned above = sf - t8;
#pragma unroll
            for (int i = 0; i < 8; ++i) {
                const unsigned sb = above + l8[i];
                const unsigned sn = above + ((i < 7) ? l8[i + 1] : 0u);
                if (sb >= rem && sn < rem) {
                    s_sel[0] = (unsigned)(tid * 8 + i);
                    s_sel[1] = rem - sn;
                }
            }
        }
        __syncthreads();
        prefix |= s_sel[0] << SHIFT[pass];
        rem     = s_sel[1];
        __syncthreads();
    }

    const float th = __uint_as_float(prefix);
    const float t  = thr[iter];

    float4 ov;
    float* po = reinterpret_cast<float*>(&ov);
#pragma unroll
    for (int e = 0; e < 4; ++e) {
        const float x = va[e];
        const float a = fabsf(x);
        po[e] = (a >= t && a >= th) ? x : copysignf(fmaxf(a - t, 0.0f), x);
    }
    reinterpret_cast<float4*>(U + (size_t)row * N_DIM)[tid] = ov;
}

// ---------------------------------------------------------------------------
extern "C" void kernel_launch(void* const* d_in, const int* in_sizes, int n_in,
                              void* d_out, int out_size)
{
    const float* x   = (const float*)d_in[0];   // [B, M]
    const float* A   = (const float*)d_in[1];   // [M, N]
    const float* W   = (const float*)d_in[2];   // [DEPTH, N, M]
    const float* thr = (const float*)d_in[3];   // [DEPTH]
    float* uout = (float*)d_out;                // [B, N]

    float *rp, *vp, *up;
    cudaGetSymbolAddress((void**)&rp, g_r);
    cudaGetSymbolAddress((void**)&vp, g_v);
    cudaGetSymbolAddress((void**)&up, g_u);

    // kth_i = 1024 - (ceil((100 - p_i)/100 * 1024) - 1), p_i = min((i+1)*1.2, 5)
    static const int KTH[DEPTH] = {13, 25, 37, 50, 52, 52, 52, 52,
                                   52, 52, 52, 52, 52, 52, 52, 52};

    const dim3 blk(256);
    const dim3 gR(B_DIM / 128, M_DIM / 128);   // (128, 2)
    const dim3 gV(B_DIM / 128, N_DIM / 128);   // (128, 8)

    // ---- iteration 0: u = 0  =>  v = x @ W0^T ----
    gemm_nt<2><<<gV, blk>>>(x, W, nullptr, vp, M_DIM, N_DIM);
    select_shrink<<<B_DIM, blk>>>(vp, up, thr, 0, KTH[0]);

    // ---- iterations 1..15 ----
    for (int i = 1; i < DEPTH; ++i) {
        // r = x - u @ A^T
        gemm_nt<0><<<gR, blk>>>(up, A, x, rp, N_DIM, M_DIM);
        // v = u + r @ W[i]^T
        gemm_nt<1><<<gV, blk>>>(rp, W + (size_t)i * N_DIM * M_DIM, up, vp,
                                M_DIM, N_DIM);
        // u = shrinkss(v); last iteration writes straight to d_out
        select_shrink<<<B_DIM, blk>>>(vp, (i == DEPTH - 1) ? uout : up,
                                      thr, i, KTH[i]);
    }
}